// round 15
// baseline (speedup 1.0000x reference)
#include <cuda_runtime.h>
#include <cuda_bf16.h>
#include <math.h>
#include <stdint.h>

#define BATCH  128
#define SEQL   512
#define EMBED  512
#define HIDDEN 1024
#define NCLS   1000
#define NTOT   2048

#define NCTA   128
#define KSPLIT 4

typedef unsigned long long ull;
typedef unsigned int u32;
typedef signed char s8;

// ---------------- device scratch -----------------------------------------------
__device__ float g_X[2][SEQL][BATCH * HIDDEN];     // x_t @ W_in + b, per gate
__device__ float g_P[KSPLIT][BATCH * NTOT];        // k-split partials
__device__ __align__(16) s8 g_hq_hi[2][BATCH * HIDDEN]; // h int8 hi plane (ping-pong)
__device__ __align__(16) s8 g_hq_lo[2][BATCH * HIDDEN]; // h int8 lo plane
__device__ __align__(16) s8 g_Wq_hi[NTOT * HIDDEN];     // recurrent W^T int8 hi [n][k]
__device__ __align__(16) s8 g_Wq_lo[NTOT * HIDDEN];
__device__ __nv_bfloat16 g_Win_hi[NTOT * EMBED];   // input-proj W^T hi [n][k] (bf16)
__device__ __nv_bfloat16 g_Win_lo[NTOT * EMBED];
__device__ __nv_bfloat16 g_emb_hi[32000 * EMBED];  // emb table bf16 hi
__device__ __nv_bfloat16 g_emb_lo[32000 * EMBED];

__device__ unsigned g_flags[NCTA];     // full barrier arrive flags
__device__ unsigned g_release;         // full barrier release word

// ---------------- MMA / ldmatrix / cp.async helpers ----------------------------
__device__ __forceinline__ u32 smem_u32(const void* p) {
    u32 a;
    asm("{ .reg .u64 t; cvta.to.shared.u64 t, %1; cvt.u32.u64 %0, t; }" : "=r"(a) : "l"(p));
    return a;
}
__device__ __forceinline__ void ldmx4(u32* r, u32 addr) {
    asm volatile("ldmatrix.sync.aligned.m8n8.x4.shared.b16 {%0,%1,%2,%3}, [%4];"
                 : "=r"(r[0]), "=r"(r[1]), "=r"(r[2]), "=r"(r[3]) : "r"(addr));
}
__device__ __forceinline__ void mma16816(float* c, const u32* a, u32 b0, u32 b1) {
    asm volatile("mma.sync.aligned.m16n8k16.row.col.f32.bf16.bf16.f32 "
                 "{%0,%1,%2,%3}, {%4,%5,%6,%7}, {%8,%9}, {%0,%1,%2,%3};"
                 : "+f"(c[0]), "+f"(c[1]), "+f"(c[2]), "+f"(c[3])
                 : "r"(a[0]), "r"(a[1]), "r"(a[2]), "r"(a[3]), "r"(b0), "r"(b1));
}
// int8 MMA: m16n8k32, s32 accum. Fragments are byte-compatible with the b16
// ldmatrix pattern (each b16 = 2 s8, k doubled).
__device__ __forceinline__ void mma16832s8(int* c, const u32* a, u32 b0, u32 b1) {
    asm volatile("mma.sync.aligned.m16n8k32.row.col.s32.s8.s8.s32 "
                 "{%0,%1,%2,%3}, {%4,%5,%6,%7}, {%8,%9}, {%0,%1,%2,%3};"
                 : "+r"(c[0]), "+r"(c[1]), "+r"(c[2]), "+r"(c[3])
                 : "r"(a[0]), "r"(a[1]), "r"(a[2]), "r"(a[3]), "r"(b0), "r"(b1));
}
#define CP16(dst, src) \
    asm volatile("cp.async.cg.shared.global [%0], [%1], 16;" :: "r"(dst), "l"(src) : "memory")
#define CP_COMMIT() asm volatile("cp.async.commit_group;" ::: "memory")
#define CP_WAIT1()  asm volatile("cp.async.wait_group 1;" ::: "memory")
#define CP_WAIT0()  asm volatile("cp.async.wait_group 0;" ::: "memory")

// ---------------- full barrier (two-stage: flags -> CTA0 -> release) ------------
__device__ __forceinline__ void full_barrier(int cta, unsigned gen) {
    __syncthreads();
    if (threadIdx.x == 0) {
        __threadfence();
        *((volatile unsigned*)&g_flags[cta]) = gen;
    }
    if (cta == 0) {
        if (threadIdx.x < NCTA) {
            while (*((volatile unsigned*)&g_flags[threadIdx.x]) < gen) { }
        }
        __syncthreads();
        if (threadIdx.x == 0) {
            __threadfence();
            *((volatile unsigned*)&g_release) = gen;
        }
    }
    if (threadIdx.x == 0) {
        while (*((volatile unsigned*)&g_release) < gen) { }
        __threadfence();
    }
    __syncthreads();
}

// ---------------- init ------------------------------------------------------------
__global__ void init_kernel() {
    int i = blockIdx.x * 256 + threadIdx.x;           // 0..131071
    g_hq_hi[0][i] = 0; g_hq_hi[1][i] = 0;
    g_hq_lo[0][i] = 0; g_hq_lo[1][i] = 0;
    if (i < NCTA) g_flags[i] = 0;
    if (i == 0) g_release = 0;
}

// ---------------- emb table -> bf16 hi/lo ------------------------------------------
__global__ void conv_emb(const float* __restrict__ emb) {
    long i = (long)blockIdx.x * 256 + threadIdx.x;
    float4 v = *(const float4*)&emb[i * 4];
    float f[4] = {v.x, v.y, v.z, v.w};
    unsigned short hiu[4], lou[4];
#pragma unroll
    for (int j = 0; j < 4; j++) {
        __nv_bfloat16 hb = __float2bfloat16_rn(f[j]);
        __nv_bfloat16 lb = __float2bfloat16_rn(f[j] - __bfloat162float(hb));
        hiu[j] = __bfloat16_as_ushort(hb);
        lou[j] = __bfloat16_as_ushort(lb);
    }
    *(ull*)&g_emb_hi[i * 4] = (ull)hiu[0] | ((ull)hiu[1] << 16) | ((ull)hiu[2] << 32) | ((ull)hiu[3] << 48);
    *(ull*)&g_emb_lo[i * 4] = (ull)lou[0] | ((ull)lou[1] << 16) | ((ull)lou[2] << 32) | ((ull)lou[3] << 48);
}

// ---------------- weight prep: recurrent part -> int8 planes (k in [512,1536)) -----
// wq = round(w * 2^20); hi = (wq+128)>>8, lo = wq - hi*256. |wq| <= 26762.
__global__ void prep_weights(const float* __restrict__ Wz,
                             const float* __restrict__ Wh)
{
    __shared__ float tile[32][33];
    const int k0  = blockIdx.x * 32;
    const int n0g = blockIdx.y * 32;
    const float* W = (n0g < 1024) ? Wz : Wh;
    const int nc0 = n0g & 1023;

    for (int r = threadIdx.y; r < 32; r += 8)
        tile[r][threadIdx.x] = W[(long)(512 + k0 + r) * HIDDEN + nc0 + threadIdx.x];
    __syncthreads();
    for (int r2 = threadIdx.y; r2 < 32; r2 += 8) {
        float v = tile[threadIdx.x][r2];
        int wq = __float2int_rn(v * 1048576.0f);       // 2^20
        int hi = (wq + 128) >> 8;
        int lo = wq - (hi << 8);
        long o = (long)(n0g + r2) * HIDDEN + k0 + threadIdx.x;
        g_Wq_hi[o] = (s8)hi;
        g_Wq_lo[o] = (s8)lo;
    }
}

// ---------------- weight prep: input part (k in [0,512)) — bf16 path ---------------
__global__ void prep_win(const float* __restrict__ Wz,
                         const float* __restrict__ Wh)
{
    __shared__ float tile[32][33];
    const int k0  = blockIdx.x * 32;
    const int n0g = blockIdx.y * 32;
    const float* W = (n0g < 1024) ? Wz : Wh;
    const int nc0 = n0g & 1023;

    for (int r = threadIdx.y; r < 32; r += 8)
        tile[r][threadIdx.x] = W[(long)(k0 + r) * HIDDEN + nc0 + threadIdx.x];
    __syncthreads();
    for (int r2 = threadIdx.y; r2 < 32; r2 += 8) {
        float v = tile[threadIdx.x][r2];
        __nv_bfloat16 hi = __float2bfloat16_rn(v);
        __nv_bfloat16 lo = __float2bfloat16_rn(v - __bfloat162float(hi));
        long o = (long)(n0g + r2) * EMBED + k0 + threadIdx.x;
        g_Win_hi[o] = hi;
        g_Win_lo[o] = lo;
    }
}

// ---------------- Kernel 1: HMMA embedding projection (bf16, unchanged) ------------
#define E_STRB 144
#define E_MAT  18432
#define E_BUF  (4 * E_MAT)
#define E_SIDX (2 * E_BUF)
#define SMEM_EMBED (E_SIDX + 512)

__global__ __launch_bounds__(256, 1) void gemm_embed_mma(
    const int*   __restrict__ x,
    const float* __restrict__ bz,
    const float* __restrict__ bh)
{
    extern __shared__ char smem[];
    const u32 sbase = smem_u32(smem);
    const int tid = threadIdx.x;
    const int wid = tid >> 5, lane = tid & 31;
    const int n0 = blockIdx.x * 128;
    const int m0 = blockIdx.y * 128;

    int* sidx = (int*)(smem + E_SIDX);
    if (tid < 128) sidx[tid] = x[m0 + tid];
    __syncthreads();

    const int srow[4] = { (tid + 0)   >> 3, (tid + 256) >> 3,
                          (tid + 512) >> 3, (tid + 768) >> 3 };
    const int sc = tid & 7;

    auto issue_tile = [&](int kt, int b) {
        const int k0 = kt * 64;
#pragma unroll
        for (int j = 0; j < 4; j++) {
            int row = srow[j];
            u32 dst = sbase + b * E_BUF + row * E_STRB + sc * 16;
            long aoff = (long)sidx[row] * EMBED + k0 + sc * 8;
            long boff = (long)(n0 + row) * EMBED + k0 + sc * 8;
            CP16(dst,             (const void*)&g_emb_hi[aoff]);
            CP16(dst + E_MAT,     (const void*)&g_emb_lo[aoff]);
            CP16(dst + 2 * E_MAT, (const void*)&g_Win_hi[boff]);
            CP16(dst + 3 * E_MAT, (const void*)&g_Win_lo[boff]);
        }
        CP_COMMIT();
    };

    const int m_base = (wid & 3) * 32;
    const int n_base = (wid >> 2) * 64;
    const u32 a_row = (u32)(lane & 15);
    const u32 b_row = (u32)((((lane >> 3) & 1) * 8) + (lane & 7));
    const u32 khalf = (u32)((lane >> 4) * 16);

    float c[2][8][4];
#pragma unroll
    for (int mi = 0; mi < 2; mi++)
#pragma unroll
        for (int nf = 0; nf < 8; nf++)
#pragma unroll
            for (int r = 0; r < 4; r++) c[mi][nf][r] = 0.0f;

    issue_tile(0, 0);

    for (int kt = 0; kt < 8; kt++) {
        if (kt < 7) { issue_tile(kt + 1, (kt + 1) & 1); CP_WAIT1(); }
        else        { CP_WAIT0(); }
        __syncthreads();

        const u32 base = sbase + (kt & 1) * E_BUF;
#pragma unroll
        for (int k16 = 0; k16 < 4; k16++) {
            const u32 kb = (u32)(k16 * 32) + khalf;
            u32 ah[2][4], al[2][4], bhv[4][4], blv[4][4];
#pragma unroll
            for (int mi = 0; mi < 2; mi++) {
                u32 ar = base + (m_base + mi * 16 + a_row) * E_STRB + kb;
                ldmx4(ah[mi], ar);
                ldmx4(al[mi], ar + E_MAT);
            }
#pragma unroll
            for (int nb = 0; nb < 4; nb++) {
                u32 br = base + 2 * E_MAT + (n_base + nb * 16 + b_row) * E_STRB + kb;
                ldmx4(bhv[nb], br);
                ldmx4(blv[nb], br + E_MAT);
            }
#pragma unroll
            for (int mi = 0; mi < 2; mi++) {
#pragma unroll
                for (int nf = 0; nf < 8; nf++) {
                    int nb = nf >> 1, hf = nf & 1;
                    mma16816(c[mi][nf], ah[mi], bhv[nb][hf], bhv[nb][2 + hf]);
                    mma16816(c[mi][nf], ah[mi], blv[nb][hf], blv[nb][2 + hf]);
                    mma16816(c[mi][nf], al[mi], bhv[nb][hf], bhv[nb][2 + hf]);
                }
            }
        }
        __syncthreads();
    }

    const int g  = n0 >> 10;
    const int j0 = n0 & 1023;
    const float* bias = g ? bh : bz;
    const int grp = lane >> 2, tg = lane & 3;

#pragma unroll
    for (int nf = 0; nf < 8; nf++) {
        int col = j0 + n_base + nf * 8 + tg * 2;
        float bv0 = bias[col], bv1 = bias[col + 1];
#pragma unroll
        for (int mi = 0; mi < 2; mi++) {
            int r0 = m0 + m_base + mi * 16 + grp;
            int b0i = r0 >> 9, t0 = r0 & 511;
            *(float2*)&g_X[g][t0][b0i * HIDDEN + col] =
                make_float2(c[mi][nf][0] + bv0, c[mi][nf][1] + bv1);
            int r1 = r0 + 8;
            int b1i = r1 >> 9, t1 = r1 & 511;
            *(float2*)&g_X[g][t1][b1i * HIDDEN + col] =
                make_float2(c[mi][nf][2] + bv0, c[mi][nf][3] + bv1);
        }
    }
}

// ---------------- Kernel 2: persistent INT8 recurrence -----------------------------
// rows are 256 int8 = 16 chunks of 16B, padded to 17 chunks (272 B) -> conflict-free
#define STRI 272
#define OFF_AHI 0
#define OFF_ALO (OFF_AHI + 128 * STRI)      // 34816
#define OFF_BHI (OFF_ALO + 128 * STRI)      // 69632
#define OFF_BLO (OFF_BHI + 64 * STRI)       // 87040
#define SMEM_PERSIST (OFF_BLO + 64 * STRI)  // 104448

__global__ __launch_bounds__(256, 1) void recurrent_persistent()
{
    extern __shared__ char smem[];
    const u32 sbase = smem_u32(smem);
    const int tid  = threadIdx.x;
    const int wid  = tid >> 5, lane = tid & 31;
    const int cta  = blockIdx.x;
    const int ks   = cta & 3;
    const int n0   = (cta >> 2) * 64;
    const int kbase = ks * 256;

    // resident B tiles (int8 weight planes): 64 rows x 16 chunks x 2 planes
#pragma unroll
    for (int it = 0; it < 4; it++) {
        int idx = tid + it * 256;            // 0..1023
        int row = idx >> 4;                  // 0..63
        int c   = idx & 15;
        long src = (long)(n0 + row) * HIDDEN + kbase + c * 16;
        *(uint4*)(smem + OFF_BHI + row * STRI + c * 16) = *(const uint4*)&g_Wq_hi[src];
        *(uint4*)(smem + OFF_BLO + row * STRI + c * 16) = *(const uint4*)&g_Wq_lo[src];
    }
    __syncthreads();

    const int wm = wid & 3, wn = wid >> 2;
    const int m_base = wm * 32, n_base = wn * 32;
    const int grp = lane >> 2, tg = lane & 3;

    const u32 a_row = (u32)(lane & 15);
    const u32 b_row = (u32)((((lane >> 3) & 1) * 8) + (lane & 7));
    const u32 khalf = (u32)((lane >> 4) * 16);   // 16B half within 32B k-step

    const u32 aHi0 = sbase + OFF_AHI + (m_base + a_row) * STRI + khalf;
    const u32 aLo0 = sbase + OFF_ALO + (m_base + a_row) * STRI + khalf;
    const u32 bHi0 = sbase + OFF_BHI + (n_base + b_row) * STRI + khalf;
    const u32 bLo0 = sbase + OFF_BLO + (n_base + b_row) * STRI + khalf;

    // reduce-phase assignment: 4 consecutive h elements per thread (row-contiguous)
    const int ubase = (cta * 256 + tid) * 4;
    const int um = ubase >> 10;
    const int uj = ubase & 1023;

    // register-carried hidden state (fp32, exact across steps)
    float hreg[4] = {0.0f, 0.0f, 0.0f, 0.0f};

    unsigned gen = 0;

    for (int t = 0; t < SEQL; t++) {
        const int par = t & 1;
        const s8* hqh = g_hq_hi[par];
        const s8* hql = g_hq_lo[par];

        // ---- issue cp.async A staging: two K halves of 128 int8 cols each ----
#pragma unroll
        for (int h = 0; h < 2; h++) {
#pragma unroll
            for (int it = 0; it < 4; it++) {
                int idx = tid + it * 256;        // 0..1023
                int row = idx >> 3;              // 0..127
                int c   = (idx & 7) + h * 8;     // 16B-chunk id along k
                long src = (long)row * HIDDEN + kbase + c * 16;
                u32 dst = sbase + OFF_AHI + row * STRI + c * 16;
                CP16(dst, (const void*)&hqh[src]);
                CP16(dst + (OFF_ALO - OFF_AHI), (const void*)&hql[src]);
            }
            CP_COMMIT();
        }

        // prefetch this step's input-projection values (DRAM) for the reduce phase
        float4 zs = *(const float4*)&g_X[0][t][um * HIDDEN + uj];
        float4 hs = *(const float4*)&g_X[1][t][um * HIDDEN + uj];

        int chh[2][4][4], cx[2][4][4];
#pragma unroll
        for (int mi = 0; mi < 2; mi++)
#pragma unroll
            for (int nf = 0; nf < 4; nf++)
#pragma unroll
                for (int r = 0; r < 4; r++) { chh[mi][nf][r] = 0; cx[mi][nf][r] = 0; }

        // ---- MMA: 2 halves x 4 k32-steps; half 1 overlapped with half 0 compute ----
#pragma unroll
        for (int half = 0; half < 2; half++) {
            if (half == 0) { CP_WAIT1(); }
            else           { CP_WAIT0(); }
            __syncthreads();
#pragma unroll
            for (int kk = 0; kk < 4; kk++) {
                const u32 kb = (u32)((half * 4 + kk) * 32);   // 32 bytes per k-step
                u32 ah[2][4], al[2][4], bhv[2][4], blv[2][4];
#pragma unroll
                for (int mi = 0; mi < 2; mi++) {
                    ldmx4(ah[mi], aHi0 + mi * 16 * STRI + kb);
                    ldmx4(al[mi], aLo0 + mi * 16 * STRI + kb);
                }
#pragma unroll
                for (int nb = 0; nb < 2; nb++) {
                    ldmx4(bhv[nb], bHi0 + nb * 16 * STRI + kb);
                    ldmx4(blv[nb], bLo0 + nb * 16 * STRI + kb);
                }
#pragma unroll
                for (int mi = 0; mi < 2; mi++) {
#pragma unroll
                    for (int nf = 0; nf < 4; nf++) {
                        int nb = nf >> 1, hf = nf & 1;
                        mma16832s8(chh[mi][nf], ah[mi], bhv[nb][hf], bhv[nb][2 + hf]);
                        mma16832s8(cx[mi][nf],  ah[mi], blv[nb][hf], blv[nb][2 + hf]);
                        mma16832s8(cx[mi][nf],  al[mi], bhv[nb][hf], bhv[nb][2 + hf]);
                    }
                }
            }
        }

        // ---- epilogue: dequant partials -> g_P (L1-bypass) ----
        // value = chh * 2^-18 + cx * 2^-26
        const float C1 = 3.814697265625e-06f;       // 2^-18
        const float C2 = 1.4901161193847656e-08f;   // 2^-26
#pragma unroll
        for (int mi = 0; mi < 2; mi++) {
#pragma unroll
            for (int nf = 0; nf < 4; nf++) {
                int row = m_base + mi * 16 + grp;
                int col = n0 + n_base + nf * 8 + tg * 2;
                float v0 = (float)chh[mi][nf][0] * C1 + (float)cx[mi][nf][0] * C2;
                float v1 = (float)chh[mi][nf][1] * C1 + (float)cx[mi][nf][1] * C2;
                float v2 = (float)chh[mi][nf][2] * C1 + (float)cx[mi][nf][2] * C2;
                float v3 = (float)chh[mi][nf][3] * C1 + (float)cx[mi][nf][3] * C2;
                __stcg((float2*)&g_P[ks][row * NTOT + col], make_float2(v0, v1));
                __stcg((float2*)&g_P[ks][(row + 8) * NTOT + col], make_float2(v2, v3));
            }
        }

        full_barrier(cta, ++gen);

        // ---- reduce + gate + update: one float4 per thread, fully coalesced ----
        {
#pragma unroll
            for (int s = 0; s < KSPLIT; s++) {
                float4 pz = __ldcg((const float4*)&g_P[s][um * NTOT + uj]);
                float4 ph = __ldcg((const float4*)&g_P[s][um * NTOT + 1024 + uj]);
                zs.x += pz.x; zs.y += pz.y; zs.z += pz.z; zs.w += pz.w;
                hs.x += ph.x; hs.y += ph.y; hs.z += ph.z; hs.w += ph.w;
            }
            float zv[4] = {zs.x, zs.y, zs.z, zs.w};
            float hv[4] = {hs.x, hs.y, hs.z, hs.w};
            u32 hipack = 0, lopack = 0;
#pragma unroll
            for (int i = 0; i < 4; i++) {
                float z  = 1.0f / (1.0f + __expf(-zv[i]));
                float hn = hreg[i] + z * (tanhf(hv[i]) - hreg[i]);
                hreg[i] = hn;                              // carry in registers
                int hq  = __float2int_rn(hn * 16384.0f);   // |hq| <= 16384
                int hi8 = (hq + 128) >> 8;                 // [-64, 64]
                int lo8 = hq - (hi8 << 8);                 // [-128, 127]
                hipack |= ((u32)(hi8 & 0xFF)) << (8 * i);
                lopack |= ((u32)(lo8 & 0xFF)) << (8 * i);
            }
            __stcg((u32*)&g_hq_hi[par ^ 1][um * HIDDEN + uj], hipack);
            __stcg((u32*)&g_hq_lo[par ^ 1][um * HIDDEN + uj], lopack);
        }

        full_barrier(cta, ++gen);
    }
}

// ---------------- Kernel 3: final FC -------------------------------------------------
__global__ __launch_bounds__(128) void fc_kernel(
    const float* __restrict__ Wfc,
    const float* __restrict__ bfc,
    float* __restrict__ out)
{
    extern __shared__ float hsm[];
    const int b0 = blockIdx.y * 16;
    const int tid = threadIdx.x;

    const float HS = 6.103515625e-05f;   // 2^-14
    for (int i = tid; i < 16 * HIDDEN / 4; i += 128) {
        u32 hi4 = *(const u32*)&g_hq_hi[0][b0 * HIDDEN + i * 4];
        u32 lo4 = *(const u32*)&g_hq_lo[0][b0 * HIDDEN + i * 4];
        float4 v;
        float* vp = (float*)&v;
#pragma unroll
        for (int j = 0; j < 4; j++) {
            // EXPLICIT sign extension: plain char is UNSIGNED on aarch64!
            int hi = (int)(s8)((hi4 >> (8 * j)) & 0xFF);
            int lo = (int)(s8)((lo4 >> (8 * j)) & 0xFF);
            vp[j] = (float)(hi * 256 + lo) * HS;
        }
        ((float4*)hsm)[i] = v;
    }
    __syncthreads();

    const int n = blockIdx.x * 128 + tid;
    if (n >= NCLS) return;

    float acc[16];
#pragma unroll
    for (int i = 0; i < 16; i++) acc[i] = 0.0f;

    for (int k = 0; k < HIDDEN; k += 4) {
        float w0 = Wfc[(long)(k + 0) * NCLS + n];
        float w1 = Wfc[(long)(k + 1) * NCLS + n];
        float w2 = Wfc[(long)(k + 2) * NCLS + n];
        float w3 = Wfc[(long)(k + 3) * NCLS + n];
#pragma unroll
        for (int i = 0; i < 16; i++) {
            float4 h4 = *(const float4*)&hsm[i * HIDDEN + k];
            acc[i] += w0 * h4.x + w1 * h4.y + w2 * h4.z + w3 * h4.w;
        }
    }
    float bv = bfc[n];
#pragma unroll
    for (int i = 0; i < 16; i++)
        out[(long)(b0 + i) * NCLS + n] = acc[i] + bv;
}

// ---------------- launch ---------------------------------------------------------------
extern "C" void kernel_launch(void* const* d_in, const int* in_sizes, int n_in,
                              void* d_out, int out_size)
{
    const int*   x   = (const int*)d_in[0];
    const float* emb = (const float*)d_in[1];
    const float* Wz  = (const float*)d_in[2];
    const float* bz  = (const float*)d_in[3];
    const float* Wh  = (const float*)d_in[4];
    const float* bh  = (const float*)d_in[5];
    const float* Wfc = (const float*)d_in[6];
    const float* bfc = (const float*)d_in[7];
    float* out = (float*)d_out;

    cudaFuncSetAttribute(gemm_embed_mma,
                         cudaFuncAttributeMaxDynamicSharedMemorySize, SMEM_EMBED);
    cudaFuncSetAttribute(recurrent_persistent,
                         cudaFuncAttributeMaxDynamicSharedMemorySize, SMEM_PERSIST);
    cudaFuncSetAttribute(fc_kernel,
                         cudaFuncAttributeMaxDynamicSharedMemorySize, 16 * HIDDEN * 4);

    init_kernel<<<512, 256>>>();
    conv_emb<<<16000, 256>>>(emb);
    prep_weights<<<dim3(32, 64), dim3(32, 8)>>>(Wz, Wh);
    prep_win<<<dim3(16, 64), dim3(32, 8)>>>(Wz, Wh);
    gemm_embed_mma<<<dim3(16, 512), 256, SMEM_EMBED>>>(x, bz, bh);
    recurrent_persistent<<<NCTA, 256, SMEM_PERSIST>>>();
    fc_kernel<<<dim3(8, 8), 128, 16 * HIDDEN * 4>>>(Wfc, bfc, out);
}

// round 16
// speedup vs baseline: 2.0758x; 2.0758x over previous
#include <cuda_runtime.h>
#include <cuda_bf16.h>
#include <cuda_fp16.h>
#include <math.h>
#include <stdint.h>

#define BATCH  128
#define SEQL   512
#define EMBED  512
#define HIDDEN 1024
#define NCLS   1000
#define NTOT   2048

#define NCTA   128
#define KSPLIT 4

typedef unsigned long long ull;
typedef unsigned int u32;

// ---------------- device scratch -----------------------------------------------
__device__ float g_X[2][SEQL][BATCH * HIDDEN];     // x_t @ W_in + b, per gate
__device__ float g_P[KSPLIT][BATCH * NTOT];        // k-split partials
__device__ __half g_hf[2][BATCH * HIDDEN];         // h state, fp16 (ping-pong)
__device__ __half g_Wtf[NTOT * HIDDEN];            // recurrent W^T fp16 [n][k]
__device__ __nv_bfloat16 g_Win_hi[NTOT * EMBED];   // input-proj W^T hi [n][k] (bf16)
__device__ __nv_bfloat16 g_Win_lo[NTOT * EMBED];
__device__ __nv_bfloat16 g_emb_hi[32000 * EMBED];  // emb table bf16 hi
__device__ __nv_bfloat16 g_emb_lo[32000 * EMBED];

__device__ unsigned g_flags[NCTA];     // full barrier arrive flags
__device__ unsigned g_release;         // full barrier release word

// ---------------- MMA / ldmatrix / cp.async helpers ----------------------------
__device__ __forceinline__ u32 smem_u32(const void* p) {
    u32 a;
    asm("{ .reg .u64 t; cvta.to.shared.u64 t, %1; cvt.u32.u64 %0, t; }" : "=r"(a) : "l"(p));
    return a;
}
__device__ __forceinline__ void ldmx4(u32* r, u32 addr) {
    asm volatile("ldmatrix.sync.aligned.m8n8.x4.shared.b16 {%0,%1,%2,%3}, [%4];"
                 : "=r"(r[0]), "=r"(r[1]), "=r"(r[2]), "=r"(r[3]) : "r"(addr));
}
__device__ __forceinline__ void mma16816bf(float* c, const u32* a, u32 b0, u32 b1) {
    asm volatile("mma.sync.aligned.m16n8k16.row.col.f32.bf16.bf16.f32 "
                 "{%0,%1,%2,%3}, {%4,%5,%6,%7}, {%8,%9}, {%0,%1,%2,%3};"
                 : "+f"(c[0]), "+f"(c[1]), "+f"(c[2]), "+f"(c[3])
                 : "r"(a[0]), "r"(a[1]), "r"(a[2]), "r"(a[3]), "r"(b0), "r"(b1));
}
__device__ __forceinline__ void mma16816f(float* c, const u32* a, u32 b0, u32 b1) {
    asm volatile("mma.sync.aligned.m16n8k16.row.col.f32.f16.f16.f32 "
                 "{%0,%1,%2,%3}, {%4,%5,%6,%7}, {%8,%9}, {%0,%1,%2,%3};"
                 : "+f"(c[0]), "+f"(c[1]), "+f"(c[2]), "+f"(c[3])
                 : "r"(a[0]), "r"(a[1]), "r"(a[2]), "r"(a[3]), "r"(b0), "r"(b1));
}
#define CP16(dst, src) \
    asm volatile("cp.async.cg.shared.global [%0], [%1], 16;" :: "r"(dst), "l"(src) : "memory")
#define CP_COMMIT() asm volatile("cp.async.commit_group;" ::: "memory")
#define CP_WAIT1()  asm volatile("cp.async.wait_group 1;" ::: "memory")
#define CP_WAIT0()  asm volatile("cp.async.wait_group 0;" ::: "memory")

// ---------------- full barrier (two-stage: flags -> CTA0 -> release) ------------
__device__ __forceinline__ void full_barrier(int cta, unsigned gen) {
    __syncthreads();
    if (threadIdx.x == 0) {
        __threadfence();
        *((volatile unsigned*)&g_flags[cta]) = gen;
    }
    if (cta == 0) {
        if (threadIdx.x < NCTA) {
            while (*((volatile unsigned*)&g_flags[threadIdx.x]) < gen) { }
        }
        __syncthreads();
        if (threadIdx.x == 0) {
            __threadfence();
            *((volatile unsigned*)&g_release) = gen;
        }
    }
    if (threadIdx.x == 0) {
        while (*((volatile unsigned*)&g_release) < gen) { }
        __threadfence();
    }
    __syncthreads();
}

// ---------------- init ------------------------------------------------------------
__global__ void init_kernel() {
    int i = blockIdx.x * 256 + threadIdx.x;           // 0..131071
    g_hf[0][i] = __float2half(0.0f);
    g_hf[1][i] = __float2half(0.0f);
    if (i < NCTA) g_flags[i] = 0;
    if (i == 0) g_release = 0;
}

// ---------------- emb table -> bf16 hi/lo ------------------------------------------
__global__ void conv_emb(const float* __restrict__ emb) {
    long i = (long)blockIdx.x * 256 + threadIdx.x;
    float4 v = *(const float4*)&emb[i * 4];
    float f[4] = {v.x, v.y, v.z, v.w};
    unsigned short hiu[4], lou[4];
#pragma unroll
    for (int j = 0; j < 4; j++) {
        __nv_bfloat16 hb = __float2bfloat16_rn(f[j]);
        __nv_bfloat16 lb = __float2bfloat16_rn(f[j] - __bfloat162float(hb));
        hiu[j] = __bfloat16_as_ushort(hb);
        lou[j] = __bfloat16_as_ushort(lb);
    }
    *(ull*)&g_emb_hi[i * 4] = (ull)hiu[0] | ((ull)hiu[1] << 16) | ((ull)hiu[2] << 32) | ((ull)hiu[3] << 48);
    *(ull*)&g_emb_lo[i * 4] = (ull)lou[0] | ((ull)lou[1] << 16) | ((ull)lou[2] << 32) | ((ull)lou[3] << 48);
}

// ---------------- weight prep: recurrent part -> fp16 (k in [512,1536)) -----------
__global__ void prep_weights(const float* __restrict__ Wz,
                             const float* __restrict__ Wh)
{
    __shared__ float tile[32][33];
    const int k0  = blockIdx.x * 32;
    const int n0g = blockIdx.y * 32;
    const float* W = (n0g < 1024) ? Wz : Wh;
    const int nc0 = n0g & 1023;

    for (int r = threadIdx.y; r < 32; r += 8)
        tile[r][threadIdx.x] = W[(long)(512 + k0 + r) * HIDDEN + nc0 + threadIdx.x];
    __syncthreads();
    for (int r2 = threadIdx.y; r2 < 32; r2 += 8) {
        float v = tile[threadIdx.x][r2];
        long o = (long)(n0g + r2) * HIDDEN + k0 + threadIdx.x;
        g_Wtf[o] = __float2half_rn(v);
    }
}

// ---------------- weight prep: input part (k in [0,512)) — bf16 hi/lo path ---------
__global__ void prep_win(const float* __restrict__ Wz,
                         const float* __restrict__ Wh)
{
    __shared__ float tile[32][33];
    const int k0  = blockIdx.x * 32;
    const int n0g = blockIdx.y * 32;
    const float* W = (n0g < 1024) ? Wz : Wh;
    const int nc0 = n0g & 1023;

    for (int r = threadIdx.y; r < 32; r += 8)
        tile[r][threadIdx.x] = W[(long)(k0 + r) * HIDDEN + nc0 + threadIdx.x];
    __syncthreads();
    for (int r2 = threadIdx.y; r2 < 32; r2 += 8) {
        float v = tile[threadIdx.x][r2];
        __nv_bfloat16 hi = __float2bfloat16_rn(v);
        __nv_bfloat16 lo = __float2bfloat16_rn(v - __bfloat162float(hi));
        long o = (long)(n0g + r2) * EMBED + k0 + threadIdx.x;
        g_Win_hi[o] = hi;
        g_Win_lo[o] = lo;
    }
}

// ---------------- Kernel 1: HMMA embedding projection (bf16 x3, unchanged) ---------
#define E_STRB 144
#define E_MAT  18432
#define E_BUF  (4 * E_MAT)
#define E_SIDX (2 * E_BUF)
#define SMEM_EMBED (E_SIDX + 512)

__global__ __launch_bounds__(256, 1) void gemm_embed_mma(
    const int*   __restrict__ x,
    const float* __restrict__ bz,
    const float* __restrict__ bh)
{
    extern __shared__ char smem[];
    const u32 sbase = smem_u32(smem);
    const int tid = threadIdx.x;
    const int wid = tid >> 5, lane = tid & 31;
    const int n0 = blockIdx.x * 128;
    const int m0 = blockIdx.y * 128;

    int* sidx = (int*)(smem + E_SIDX);
    if (tid < 128) sidx[tid] = x[m0 + tid];
    __syncthreads();

    const int srow[4] = { (tid + 0)   >> 3, (tid + 256) >> 3,
                          (tid + 512) >> 3, (tid + 768) >> 3 };
    const int sc = tid & 7;

    auto issue_tile = [&](int kt, int b) {
        const int k0 = kt * 64;
#pragma unroll
        for (int j = 0; j < 4; j++) {
            int row = srow[j];
            u32 dst = sbase + b * E_BUF + row * E_STRB + sc * 16;
            long aoff = (long)sidx[row] * EMBED + k0 + sc * 8;
            long boff = (long)(n0 + row) * EMBED + k0 + sc * 8;
            CP16(dst,             (const void*)&g_emb_hi[aoff]);
            CP16(dst + E_MAT,     (const void*)&g_emb_lo[aoff]);
            CP16(dst + 2 * E_MAT, (const void*)&g_Win_hi[boff]);
            CP16(dst + 3 * E_MAT, (const void*)&g_Win_lo[boff]);
        }
        CP_COMMIT();
    };

    const int m_base = (wid & 3) * 32;
    const int n_base = (wid >> 2) * 64;
    const u32 a_row = (u32)(lane & 15);
    const u32 b_row = (u32)((((lane >> 3) & 1) * 8) + (lane & 7));
    const u32 khalf = (u32)((lane >> 4) * 16);

    float c[2][8][4];
#pragma unroll
    for (int mi = 0; mi < 2; mi++)
#pragma unroll
        for (int nf = 0; nf < 8; nf++)
#pragma unroll
            for (int r = 0; r < 4; r++) c[mi][nf][r] = 0.0f;

    issue_tile(0, 0);

    for (int kt = 0; kt < 8; kt++) {
        if (kt < 7) { issue_tile(kt + 1, (kt + 1) & 1); CP_WAIT1(); }
        else        { CP_WAIT0(); }
        __syncthreads();

        const u32 base = sbase + (kt & 1) * E_BUF;
#pragma unroll
        for (int k16 = 0; k16 < 4; k16++) {
            const u32 kb = (u32)(k16 * 32) + khalf;
            u32 ah[2][4], al[2][4], bhv[4][4], blv[4][4];
#pragma unroll
            for (int mi = 0; mi < 2; mi++) {
                u32 ar = base + (m_base + mi * 16 + a_row) * E_STRB + kb;
                ldmx4(ah[mi], ar);
                ldmx4(al[mi], ar + E_MAT);
            }
#pragma unroll
            for (int nb = 0; nb < 4; nb++) {
                u32 br = base + 2 * E_MAT + (n_base + nb * 16 + b_row) * E_STRB + kb;
                ldmx4(bhv[nb], br);
                ldmx4(blv[nb], br + E_MAT);
            }
#pragma unroll
            for (int mi = 0; mi < 2; mi++) {
#pragma unroll
                for (int nf = 0; nf < 8; nf++) {
                    int nb = nf >> 1, hf = nf & 1;
                    mma16816bf(c[mi][nf], ah[mi], bhv[nb][hf], bhv[nb][2 + hf]);
                    mma16816bf(c[mi][nf], ah[mi], blv[nb][hf], blv[nb][2 + hf]);
                    mma16816bf(c[mi][nf], al[mi], bhv[nb][hf], bhv[nb][2 + hf]);
                }
            }
        }
        __syncthreads();
    }

    const int g  = n0 >> 10;
    const int j0 = n0 & 1023;
    const float* bias = g ? bh : bz;
    const int grp = lane >> 2, tg = lane & 3;

#pragma unroll
    for (int nf = 0; nf < 8; nf++) {
        int col = j0 + n_base + nf * 8 + tg * 2;
        float bv0 = bias[col], bv1 = bias[col + 1];
#pragma unroll
        for (int mi = 0; mi < 2; mi++) {
            int r0 = m0 + m_base + mi * 16 + grp;
            int b0i = r0 >> 9, t0 = r0 & 511;
            *(float2*)&g_X[g][t0][b0i * HIDDEN + col] =
                make_float2(c[mi][nf][0] + bv0, c[mi][nf][1] + bv1);
            int r1 = r0 + 8;
            int b1i = r1 >> 9, t1 = r1 & 511;
            *(float2*)&g_X[g][t1][b1i * HIDDEN + col] =
                make_float2(c[mi][nf][2] + bv0, c[mi][nf][3] + bv1);
        }
    }
}

// ---------------- Kernel 2: persistent FP16 recurrence (single product) -----------
// rows: 256 fp16 = 512B = 32 chunks of 16B, padded to 33 (528B) -> conflict-free
#define STRH 528
#define OFF_A 0
#define OFF_B (OFF_A + 128 * STRH)          // 67584
#define SMEM_PERSIST (OFF_B + 64 * STRH)    // 101376

__global__ __launch_bounds__(256, 1) void recurrent_persistent()
{
    extern __shared__ char smem[];
    const u32 sbase = smem_u32(smem);
    const int tid  = threadIdx.x;
    const int wid  = tid >> 5, lane = tid & 31;
    const int cta  = blockIdx.x;
    const int ks   = cta & 3;
    const int n0   = (cta >> 2) * 64;
    const int kbase = ks * 256;

    // resident B tile (fp16 weights): 64 rows x 32 chunks
#pragma unroll
    for (int it = 0; it < 8; it++) {
        int idx = tid + it * 256;            // 0..2047
        int row = idx >> 5;                  // 0..63
        int c   = idx & 31;
        long src = (long)(n0 + row) * HIDDEN + kbase + c * 8;
        *(uint4*)(smem + OFF_B + row * STRH + c * 16) = *(const uint4*)&g_Wtf[src];
    }
    __syncthreads();

    const int wm = wid & 3, wn = wid >> 2;
    const int m_base = wm * 32, n_base = wn * 32;
    const int grp = lane >> 2, tg = lane & 3;

    const u32 a_row = (u32)(lane & 15);
    const u32 b_row = (u32)((((lane >> 3) & 1) * 8) + (lane & 7));
    const u32 khalf = (u32)((lane >> 4) * 16);

    const u32 aF0 = sbase + OFF_A + (m_base + a_row) * STRH + khalf;
    const u32 bF0 = sbase + OFF_B + (n_base + b_row) * STRH + khalf;

    // reduce-phase assignment: 4 consecutive h elements per thread (row-contiguous)
    const int ubase = (cta * 256 + tid) * 4;
    const int um = ubase >> 10;
    const int uj = ubase & 1023;

    // register-carried hidden state (fp32, exact across steps)
    float hreg[4] = {0.0f, 0.0f, 0.0f, 0.0f};

    unsigned gen = 0;

    for (int t = 0; t < SEQL; t++) {
        const int par = t & 1;
        const __half* hf = g_hf[par];

        // ---- issue cp.async A staging: two K halves of 128 fp16 cols each ----
#pragma unroll
        for (int h = 0; h < 2; h++) {
#pragma unroll
            for (int it = 0; it < 4; it++) {
                int idx = tid + it * 256;        // 0..1023
                int row = idx >> 3;              // 0..127
                int c   = (idx & 7) + h * 16;    // wait: 16 chunks per half
                // fix: 128 fp16 = 256B = 16 chunks; idx&7 gives 8 -> need 2 per row
                (void)row; (void)c;
            }
        }
        // correct staging: 128 rows x 16 chunks per half = 2048 -> 8 per thread
#pragma unroll
        for (int h = 0; h < 2; h++) {
#pragma unroll
            for (int it = 0; it < 8; it++) {
                int idx = tid + it * 256;        // 0..2047
                int row = idx >> 4;              // 0..127
                int c   = (idx & 15) + h * 16;   // 16B-chunk id along k
                long src = (long)row * HIDDEN + kbase + c * 8;
                u32 dst = sbase + OFF_A + row * STRH + c * 16;
                CP16(dst, (const void*)&hf[src]);
            }
            CP_COMMIT();
        }

        // prefetch this step's input-projection values (DRAM) for the reduce phase
        float4 zs = *(const float4*)&g_X[0][t][um * HIDDEN + uj];
        float4 hs = *(const float4*)&g_X[1][t][um * HIDDEN + uj];

        float c[2][4][4];
#pragma unroll
        for (int mi = 0; mi < 2; mi++)
#pragma unroll
            for (int nf = 0; nf < 4; nf++)
#pragma unroll
                for (int r = 0; r < 4; r++) c[mi][nf][r] = 0.0f;

        // ---- MMA: half 0 after wait_group 1; half 1 overlapped ----
#pragma unroll
        for (int half = 0; half < 2; half++) {
            if (half == 0) { CP_WAIT1(); }
            else           { CP_WAIT0(); }
            __syncthreads();
#pragma unroll
            for (int kk = 0; kk < 8; kk++) {
                const int k16 = half * 8 + kk;
                const u32 kb = (u32)(k16 * 32);
                u32 av[2][4], bv[2][4];
#pragma unroll
                for (int mi = 0; mi < 2; mi++)
                    ldmx4(av[mi], aF0 + mi * 16 * STRH + kb);
#pragma unroll
                for (int nb = 0; nb < 2; nb++)
                    ldmx4(bv[nb], bF0 + nb * 16 * STRH + kb);
#pragma unroll
                for (int mi = 0; mi < 2; mi++) {
#pragma unroll
                    for (int nf = 0; nf < 4; nf++) {
                        int nb = nf >> 1, hf2 = nf & 1;
                        mma16816f(c[mi][nf], av[mi], bv[nb][hf2], bv[nb][2 + hf2]);
                    }
                }
            }
        }

        // ---- epilogue: partials -> g_P (L1-bypass) ----
#pragma unroll
        for (int mi = 0; mi < 2; mi++) {
#pragma unroll
            for (int nf = 0; nf < 4; nf++) {
                int row = m_base + mi * 16 + grp;
                int col = n0 + n_base + nf * 8 + tg * 2;
                __stcg((float2*)&g_P[ks][row * NTOT + col],
                       make_float2(c[mi][nf][0], c[mi][nf][1]));
                __stcg((float2*)&g_P[ks][(row + 8) * NTOT + col],
                       make_float2(c[mi][nf][2], c[mi][nf][3]));
            }
        }

        full_barrier(cta, ++gen);

        // ---- reduce + gate + update: one float4 per thread, fully coalesced ----
        {
#pragma unroll
            for (int s = 0; s < KSPLIT; s++) {
                float4 pz = __ldcg((const float4*)&g_P[s][um * NTOT + uj]);
                float4 ph = __ldcg((const float4*)&g_P[s][um * NTOT + 1024 + uj]);
                zs.x += pz.x; zs.y += pz.y; zs.z += pz.z; zs.w += pz.w;
                hs.x += ph.x; hs.y += ph.y; hs.z += ph.z; hs.w += ph.w;
            }
            float zv[4] = {zs.x, zs.y, zs.z, zs.w};
            float hv[4] = {hs.x, hs.y, hs.z, hs.w};
            unsigned short hp[4];
#pragma unroll
            for (int i = 0; i < 4; i++) {
                float z  = 1.0f / (1.0f + __expf(-zv[i]));
                float hn = hreg[i] + z * (tanhf(hv[i]) - hreg[i]);
                hreg[i] = hn;                              // carry in registers
                hp[i] = __half_as_ushort(__float2half_rn(hn));
            }
            ull pack = (ull)hp[0] | ((ull)hp[1] << 16) | ((ull)hp[2] << 32) | ((ull)hp[3] << 48);
            __stcg((ull*)&g_hf[par ^ 1][um * HIDDEN + uj], pack);
        }

        full_barrier(cta, ++gen);
    }
}

// ---------------- Kernel 3: final FC -------------------------------------------------
__global__ __launch_bounds__(128) void fc_kernel(
    const float* __restrict__ Wfc,
    const float* __restrict__ bfc,
    float* __restrict__ out)
{
    extern __shared__ float hsm[];
    const int b0 = blockIdx.y * 16;
    const int tid = threadIdx.x;

    for (int i = tid; i < 16 * HIDDEN / 4; i += 128) {
        ull p = *(const ull*)&g_hf[0][b0 * HIDDEN + i * 4];
        float4 v;
        float* vp = (float*)&v;
#pragma unroll
        for (int j = 0; j < 4; j++)
            vp[j] = __half2float(__ushort_as_half((unsigned short)(p >> (16 * j))));
        ((float4*)hsm)[i] = v;
    }
    __syncthreads();

    const int n = blockIdx.x * 128 + tid;
    if (n >= NCLS) return;

    float acc[16];
#pragma unroll
    for (int i = 0; i < 16; i++) acc[i] = 0.0f;

    for (int k = 0; k < HIDDEN; k += 4) {
        float w0 = Wfc[(long)(k + 0) * NCLS + n];
        float w1 = Wfc[(long)(k + 1) * NCLS + n];
        float w2 = Wfc[(long)(k + 2) * NCLS + n];
        float w3 = Wfc[(long)(k + 3) * NCLS + n];
#pragma unroll
        for (int i = 0; i < 16; i++) {
            float4 h4 = *(const float4*)&hsm[i * HIDDEN + k];
            acc[i] += w0 * h4.x + w1 * h4.y + w2 * h4.z + w3 * h4.w;
        }
    }
    float bv = bfc[n];
#pragma unroll
    for (int i = 0; i < 16; i++)
        out[(long)(b0 + i) * NCLS + n] = acc[i] + bv;
}

// ---------------- launch ---------------------------------------------------------------
extern "C" void kernel_launch(void* const* d_in, const int* in_sizes, int n_in,
                              void* d_out, int out_size)
{
    const int*   x   = (const int*)d_in[0];
    const float* emb = (const float*)d_in[1];
    const float* Wz  = (const float*)d_in[2];
    const float* bz  = (const float*)d_in[3];
    const float* Wh  = (const float*)d_in[4];
    const float* bh  = (const float*)d_in[5];
    const float* Wfc = (const float*)d_in[6];
    const float* bfc = (const float*)d_in[7];
    float* out = (float*)d_out;

    cudaFuncSetAttribute(gemm_embed_mma,
                         cudaFuncAttributeMaxDynamicSharedMemorySize, SMEM_EMBED);
    cudaFuncSetAttribute(recurrent_persistent,
                         cudaFuncAttributeMaxDynamicSharedMemorySize, SMEM_PERSIST);
    cudaFuncSetAttribute(fc_kernel,
                         cudaFuncAttributeMaxDynamicSharedMemorySize, 16 * HIDDEN * 4);

    init_kernel<<<512, 256>>>();
    conv_emb<<<16000, 256>>>(emb);
    prep_weights<<<dim3(32, 64), dim3(32, 8)>>>(Wz, Wh);
    prep_win<<<dim3(16, 64), dim3(32, 8)>>>(Wz, Wh);
    gemm_embed_mma<<<dim3(16, 512), 256, SMEM_EMBED>>>(x, bz, bh);
    recurrent_persistent<<<NCTA, 256, SMEM_PERSIST>>>();
    fc_kernel<<<dim3(8, 8), 128, 16 * HIDDEN * 4>>>(Wfc, bfc, out);
}

// round 17
// speedup vs baseline: 2.3031x; 1.1095x over previous
#include <cuda_runtime.h>
#include <cuda_bf16.h>
#include <cuda_fp16.h>
#include <math.h>
#include <stdint.h>

#define BATCH  128
#define SEQL   512
#define EMBED  512
#define HIDDEN 1024
#define NCLS   1000
#define NTOT   2048

#define NCTA   128
#define KSPLIT 4

typedef unsigned long long ull;
typedef unsigned int u32;

// ---------------- device scratch -----------------------------------------------
__device__ float g_X[2][SEQL][BATCH * HIDDEN];     // x_t @ W_in + b, per gate
__device__ float g_P[KSPLIT][BATCH * NTOT];        // k-split partials
__device__ __half g_hf[2][BATCH * HIDDEN];         // h state, fp16 (ping-pong)
__device__ __half g_Wtf[NTOT * HIDDEN];            // recurrent W^T fp16 [n][k]
__device__ __half g_Win_f[NTOT * EMBED];           // input-proj W^T fp16 [n][k]
__device__ __half g_emb_f[32000 * EMBED];          // emb table fp16

__device__ unsigned g_flags[NCTA];     // full barrier arrive flags
__device__ unsigned g_release;         // full barrier release word

// ---------------- MMA / ldmatrix / cp.async helpers ----------------------------
__device__ __forceinline__ u32 smem_u32(const void* p) {
    u32 a;
    asm("{ .reg .u64 t; cvta.to.shared.u64 t, %1; cvt.u32.u64 %0, t; }" : "=r"(a) : "l"(p));
    return a;
}
__device__ __forceinline__ void ldmx4(u32* r, u32 addr) {
    asm volatile("ldmatrix.sync.aligned.m8n8.x4.shared.b16 {%0,%1,%2,%3}, [%4];"
                 : "=r"(r[0]), "=r"(r[1]), "=r"(r[2]), "=r"(r[3]) : "r"(addr));
}
__device__ __forceinline__ void mma16816f(float* c, const u32* a, u32 b0, u32 b1) {
    asm volatile("mma.sync.aligned.m16n8k16.row.col.f32.f16.f16.f32 "
                 "{%0,%1,%2,%3}, {%4,%5,%6,%7}, {%8,%9}, {%0,%1,%2,%3};"
                 : "+f"(c[0]), "+f"(c[1]), "+f"(c[2]), "+f"(c[3])
                 : "r"(a[0]), "r"(a[1]), "r"(a[2]), "r"(a[3]), "r"(b0), "r"(b1));
}
#define CP16(dst, src) \
    asm volatile("cp.async.cg.shared.global [%0], [%1], 16;" :: "r"(dst), "l"(src) : "memory")
#define CP_COMMIT() asm volatile("cp.async.commit_group;" ::: "memory")
#define CP_WAIT1()  asm volatile("cp.async.wait_group 1;" ::: "memory")
#define CP_WAIT0()  asm volatile("cp.async.wait_group 0;" ::: "memory")

// ---------------- full barrier (two-stage: flags -> CTA0 -> release) ------------
__device__ __forceinline__ void full_barrier(int cta, unsigned gen) {
    __syncthreads();
    if (threadIdx.x == 0) {
        __threadfence();
        *((volatile unsigned*)&g_flags[cta]) = gen;
    }
    if (cta == 0) {
        if (threadIdx.x < NCTA) {
            while (*((volatile unsigned*)&g_flags[threadIdx.x]) < gen) { }
        }
        __syncthreads();
        if (threadIdx.x == 0) {
            __threadfence();
            *((volatile unsigned*)&g_release) = gen;
        }
    }
    if (threadIdx.x == 0) {
        while (*((volatile unsigned*)&g_release) < gen) { }
        __threadfence();
    }
    __syncthreads();
}

// ---------------- init ------------------------------------------------------------
__global__ void init_kernel() {
    int i = blockIdx.x * 256 + threadIdx.x;           // 0..131071
    g_hf[0][i] = __float2half(0.0f);
    g_hf[1][i] = __float2half(0.0f);
    if (i < NCTA) g_flags[i] = 0;
    if (i == 0) g_release = 0;
}

// ---------------- emb table -> fp16 -------------------------------------------------
__global__ void conv_emb(const float* __restrict__ emb) {
    long i = (long)blockIdx.x * 256 + threadIdx.x;    // one float4 each
    float4 v = *(const float4*)&emb[i * 4];
    unsigned short u0 = __half_as_ushort(__float2half_rn(v.x));
    unsigned short u1 = __half_as_ushort(__float2half_rn(v.y));
    unsigned short u2 = __half_as_ushort(__float2half_rn(v.z));
    unsigned short u3 = __half_as_ushort(__float2half_rn(v.w));
    *(ull*)&g_emb_f[i * 4] = (ull)u0 | ((ull)u1 << 16) | ((ull)u2 << 32) | ((ull)u3 << 48);
}

// ---------------- weight prep: recurrent part -> fp16 (k in [512,1536)) -----------
__global__ void prep_weights(const float* __restrict__ Wz,
                             const float* __restrict__ Wh)
{
    __shared__ float tile[32][33];
    const int k0  = blockIdx.x * 32;
    const int n0g = blockIdx.y * 32;
    const float* W = (n0g < 1024) ? Wz : Wh;
    const int nc0 = n0g & 1023;

    for (int r = threadIdx.y; r < 32; r += 8)
        tile[r][threadIdx.x] = W[(long)(512 + k0 + r) * HIDDEN + nc0 + threadIdx.x];
    __syncthreads();
    for (int r2 = threadIdx.y; r2 < 32; r2 += 8) {
        float v = tile[threadIdx.x][r2];
        long o = (long)(n0g + r2) * HIDDEN + k0 + threadIdx.x;
        g_Wtf[o] = __float2half_rn(v);
    }
}

// ---------------- weight prep: input part -> fp16 (k in [0,512)) -------------------
__global__ void prep_win(const float* __restrict__ Wz,
                         const float* __restrict__ Wh)
{
    __shared__ float tile[32][33];
    const int k0  = blockIdx.x * 32;
    const int n0g = blockIdx.y * 32;
    const float* W = (n0g < 1024) ? Wz : Wh;
    const int nc0 = n0g & 1023;

    for (int r = threadIdx.y; r < 32; r += 8)
        tile[r][threadIdx.x] = W[(long)(k0 + r) * HIDDEN + nc0 + threadIdx.x];
    __syncthreads();
    for (int r2 = threadIdx.y; r2 < 32; r2 += 8) {
        float v = tile[threadIdx.x][r2];
        long o = (long)(n0g + r2) * EMBED + k0 + threadIdx.x;
        g_Win_f[o] = __float2half_rn(v);
    }
}

// ---------------- Kernel 1: fp16 HMMA embedding projection -------------------------
// C tile 128(M) x 128(N), K=512 in 8 tiles of 64, cp.async double-buffered.
// Per buffer: A (128 rows x 144B) + B (128 rows x 144B).
#define E_STRB 144
#define E_MAT  18432
#define E_BUF  (2 * E_MAT)           // 36864
#define E_SIDX (2 * E_BUF)           // 73728
#define SMEM_EMBED (E_SIDX + 512)

__global__ __launch_bounds__(256, 1) void gemm_embed_mma(
    const int*   __restrict__ x,
    const float* __restrict__ bz,
    const float* __restrict__ bh)
{
    extern __shared__ char smem[];
    const u32 sbase = smem_u32(smem);
    const int tid = threadIdx.x;
    const int wid = tid >> 5, lane = tid & 31;
    const int n0 = blockIdx.x * 128;
    const int m0 = blockIdx.y * 128;

    int* sidx = (int*)(smem + E_SIDX);
    if (tid < 128) sidx[tid] = x[m0 + tid];
    __syncthreads();

    // staging: per matrix, 128 rows x 8 chunks (16B) = 1024 -> 4 per thread
    auto issue_tile = [&](int kt, int b) {
        const int k0 = kt * 64;
#pragma unroll
        for (int j = 0; j < 4; j++) {
            int idx = tid + j * 256;           // 0..1023
            int row = idx >> 3;                // 0..127
            int c   = idx & 7;                 // 16B chunk (8 fp16)
            u32 dst = sbase + b * E_BUF + row * E_STRB + c * 16;
            long aoff = (long)sidx[row] * EMBED + k0 + c * 8;
            long boff = (long)(n0 + row) * EMBED + k0 + c * 8;
            CP16(dst,         (const void*)&g_emb_f[aoff]);
            CP16(dst + E_MAT, (const void*)&g_Win_f[boff]);
        }
        CP_COMMIT();
    };

    const int m_base = (wid & 3) * 32;
    const int n_base = (wid >> 2) * 64;
    const u32 a_row = (u32)(lane & 15);
    const u32 b_row = (u32)((((lane >> 3) & 1) * 8) + (lane & 7));
    const u32 khalf = (u32)((lane >> 4) * 16);

    float c[2][8][4];
#pragma unroll
    for (int mi = 0; mi < 2; mi++)
#pragma unroll
        for (int nf = 0; nf < 8; nf++)
#pragma unroll
            for (int r = 0; r < 4; r++) c[mi][nf][r] = 0.0f;

    issue_tile(0, 0);

    for (int kt = 0; kt < 8; kt++) {
        if (kt < 7) { issue_tile(kt + 1, (kt + 1) & 1); CP_WAIT1(); }
        else        { CP_WAIT0(); }
        __syncthreads();

        const u32 base = sbase + (kt & 1) * E_BUF;
#pragma unroll
        for (int k16 = 0; k16 < 4; k16++) {
            const u32 kb = (u32)(k16 * 32) + khalf;
            u32 av[2][4], bv[4][4];
#pragma unroll
            for (int mi = 0; mi < 2; mi++)
                ldmx4(av[mi], base + (m_base + mi * 16 + a_row) * E_STRB + kb);
#pragma unroll
            for (int nb = 0; nb < 4; nb++)
                ldmx4(bv[nb], base + E_MAT + (n_base + nb * 16 + b_row) * E_STRB + kb);
#pragma unroll
            for (int mi = 0; mi < 2; mi++) {
#pragma unroll
                for (int nf = 0; nf < 8; nf++) {
                    int nb = nf >> 1, hf = nf & 1;
                    mma16816f(c[mi][nf], av[mi], bv[nb][hf], bv[nb][2 + hf]);
                }
            }
        }
        __syncthreads();
    }

    const int g  = n0 >> 10;
    const int j0 = n0 & 1023;
    const float* bias = g ? bh : bz;
    const int grp = lane >> 2, tg = lane & 3;

#pragma unroll
    for (int nf = 0; nf < 8; nf++) {
        int col = j0 + n_base + nf * 8 + tg * 2;
        float bv0 = bias[col], bv1 = bias[col + 1];
#pragma unroll
        for (int mi = 0; mi < 2; mi++) {
            int r0 = m0 + m_base + mi * 16 + grp;
            int b0i = r0 >> 9, t0 = r0 & 511;
            *(float2*)&g_X[g][t0][b0i * HIDDEN + col] =
                make_float2(c[mi][nf][0] + bv0, c[mi][nf][1] + bv1);
            int r1 = r0 + 8;
            int b1i = r1 >> 9, t1 = r1 & 511;
            *(float2*)&g_X[g][t1][b1i * HIDDEN + col] =
                make_float2(c[mi][nf][2] + bv0, c[mi][nf][3] + bv1);
        }
    }
}

// ---------------- Kernel 2: persistent FP16 recurrence (single product) -----------
#define STRH 528
#define OFF_A 0
#define OFF_B (OFF_A + 128 * STRH)          // 67584
#define SMEM_PERSIST (OFF_B + 64 * STRH)    // 101376

__global__ __launch_bounds__(256, 1) void recurrent_persistent()
{
    extern __shared__ char smem[];
    const u32 sbase = smem_u32(smem);
    const int tid  = threadIdx.x;
    const int wid  = tid >> 5, lane = tid & 31;
    const int cta  = blockIdx.x;
    const int ks   = cta & 3;
    const int n0   = (cta >> 2) * 64;
    const int kbase = ks * 256;

    // resident B tile (fp16 weights): 64 rows x 32 chunks
#pragma unroll
    for (int it = 0; it < 8; it++) {
        int idx = tid + it * 256;            // 0..2047
        int row = idx >> 5;                  // 0..63
        int c   = idx & 31;
        long src = (long)(n0 + row) * HIDDEN + kbase + c * 8;
        *(uint4*)(smem + OFF_B + row * STRH + c * 16) = *(const uint4*)&g_Wtf[src];
    }
    __syncthreads();

    const int wm = wid & 3, wn = wid >> 2;
    const int m_base = wm * 32, n_base = wn * 32;
    const int grp = lane >> 2, tg = lane & 3;

    const u32 a_row = (u32)(lane & 15);
    const u32 b_row = (u32)((((lane >> 3) & 1) * 8) + (lane & 7));
    const u32 khalf = (u32)((lane >> 4) * 16);

    const u32 aF0 = sbase + OFF_A + (m_base + a_row) * STRH + khalf;
    const u32 bF0 = sbase + OFF_B + (n_base + b_row) * STRH + khalf;

    // reduce-phase assignment: 4 consecutive h elements per thread (row-contiguous)
    const int ubase = (cta * 256 + tid) * 4;
    const int um = ubase >> 10;
    const int uj = ubase & 1023;

    // register-carried hidden state (fp32, exact across steps)
    float hreg[4] = {0.0f, 0.0f, 0.0f, 0.0f};

    unsigned gen = 0;

    for (int t = 0; t < SEQL; t++) {
        const int par = t & 1;
        const __half* hf = g_hf[par];

        // ---- cp.async A staging: 128 rows x 16 chunks per half ----
#pragma unroll
        for (int h = 0; h < 2; h++) {
#pragma unroll
            for (int it = 0; it < 8; it++) {
                int idx = tid + it * 256;        // 0..2047
                int row = idx >> 4;              // 0..127
                int c   = (idx & 15) + h * 16;   // 16B-chunk id along k
                long src = (long)row * HIDDEN + kbase + c * 8;
                u32 dst = sbase + OFF_A + row * STRH + c * 16;
                CP16(dst, (const void*)&hf[src]);
            }
            CP_COMMIT();
        }

        // prefetch this step's input-projection values (DRAM) for the reduce phase
        float4 zs = *(const float4*)&g_X[0][t][um * HIDDEN + uj];
        float4 hs = *(const float4*)&g_X[1][t][um * HIDDEN + uj];

        float c[2][4][4];
#pragma unroll
        for (int mi = 0; mi < 2; mi++)
#pragma unroll
            for (int nf = 0; nf < 4; nf++)
#pragma unroll
                for (int r = 0; r < 4; r++) c[mi][nf][r] = 0.0f;

        // ---- MMA: half 0 after wait_group 1; half 1 overlapped ----
#pragma unroll
        for (int half = 0; half < 2; half++) {
            if (half == 0) { CP_WAIT1(); }
            else           { CP_WAIT0(); }
            __syncthreads();
#pragma unroll
            for (int kk = 0; kk < 8; kk++) {
                const int k16 = half * 8 + kk;
                const u32 kb = (u32)(k16 * 32);
                u32 av[2][4], bv[2][4];
#pragma unroll
                for (int mi = 0; mi < 2; mi++)
                    ldmx4(av[mi], aF0 + mi * 16 * STRH + kb);
#pragma unroll
                for (int nb = 0; nb < 2; nb++)
                    ldmx4(bv[nb], bF0 + nb * 16 * STRH + kb);
#pragma unroll
                for (int mi = 0; mi < 2; mi++) {
#pragma unroll
                    for (int nf = 0; nf < 4; nf++) {
                        int nb = nf >> 1, hf2 = nf & 1;
                        mma16816f(c[mi][nf], av[mi], bv[nb][hf2], bv[nb][2 + hf2]);
                    }
                }
            }
        }

        // ---- epilogue: partials -> g_P (L1-bypass) ----
#pragma unroll
        for (int mi = 0; mi < 2; mi++) {
#pragma unroll
            for (int nf = 0; nf < 4; nf++) {
                int row = m_base + mi * 16 + grp;
                int col = n0 + n_base + nf * 8 + tg * 2;
                __stcg((float2*)&g_P[ks][row * NTOT + col],
                       make_float2(c[mi][nf][0], c[mi][nf][1]));
                __stcg((float2*)&g_P[ks][(row + 8) * NTOT + col],
                       make_float2(c[mi][nf][2], c[mi][nf][3]));
            }
        }

        full_barrier(cta, ++gen);

        // ---- reduce + gate + update: one float4 per thread, fully coalesced ----
        {
#pragma unroll
            for (int s = 0; s < KSPLIT; s++) {
                float4 pz = __ldcg((const float4*)&g_P[s][um * NTOT + uj]);
                float4 ph = __ldcg((const float4*)&g_P[s][um * NTOT + 1024 + uj]);
                zs.x += pz.x; zs.y += pz.y; zs.z += pz.z; zs.w += pz.w;
                hs.x += ph.x; hs.y += ph.y; hs.z += ph.z; hs.w += ph.w;
            }
            float zv[4] = {zs.x, zs.y, zs.z, zs.w};
            float hv[4] = {hs.x, hs.y, hs.z, hs.w};
            unsigned short hp[4];
#pragma unroll
            for (int i = 0; i < 4; i++) {
                float z  = 1.0f / (1.0f + __expf(-zv[i]));
                float hn = hreg[i] + z * (tanhf(hv[i]) - hreg[i]);
                hreg[i] = hn;                              // carry in registers
                hp[i] = __half_as_ushort(__float2half_rn(hn));
            }
            ull pack = (ull)hp[0] | ((ull)hp[1] << 16) | ((ull)hp[2] << 32) | ((ull)hp[3] << 48);
            __stcg((ull*)&g_hf[par ^ 1][um * HIDDEN + uj], pack);
        }

        full_barrier(cta, ++gen);
    }
}

// ---------------- Kernel 3: final FC -------------------------------------------------
__global__ __launch_bounds__(128) void fc_kernel(
    const float* __restrict__ Wfc,
    const float* __restrict__ bfc,
    float* __restrict__ out)
{
    extern __shared__ float hsm[];
    const int b0 = blockIdx.y * 16;
    const int tid = threadIdx.x;

    for (int i = tid; i < 16 * HIDDEN / 4; i += 128) {
        ull p = *(const ull*)&g_hf[0][b0 * HIDDEN + i * 4];
        float4 v;
        float* vp = (float*)&v;
#pragma unroll
        for (int j = 0; j < 4; j++)
            vp[j] = __half2float(__ushort_as_half((unsigned short)(p >> (16 * j))));
        ((float4*)hsm)[i] = v;
    }
    __syncthreads();

    const int n = blockIdx.x * 128 + tid;
    if (n >= NCLS) return;

    float acc[16];
#pragma unroll
    for (int i = 0; i < 16; i++) acc[i] = 0.0f;

    for (int k = 0; k < HIDDEN; k += 4) {
        float w0 = Wfc[(long)(k + 0) * NCLS + n];
        float w1 = Wfc[(long)(k + 1) * NCLS + n];
        float w2 = Wfc[(long)(k + 2) * NCLS + n];
        float w3 = Wfc[(long)(k + 3) * NCLS + n];
#pragma unroll
        for (int i = 0; i < 16; i++) {
            float4 h4 = *(const float4*)&hsm[i * HIDDEN + k];
            acc[i] += w0 * h4.x + w1 * h4.y + w2 * h4.z + w3 * h4.w;
        }
    }
    float bv = bfc[n];
#pragma unroll
    for (int i = 0; i < 16; i++)
        out[(long)(b0 + i) * NCLS + n] = acc[i] + bv;
}

// ---------------- launch ---------------------------------------------------------------
extern "C" void kernel_launch(void* const* d_in, const int* in_sizes, int n_in,
                              void* d_out, int out_size)
{
    const int*   x   = (const int*)d_in[0];
    const float* emb = (const float*)d_in[1];
    const float* Wz  = (const float*)d_in[2];
    const float* bz  = (const float*)d_in[3];
    const float* Wh  = (const float*)d_in[4];
    const float* bh  = (const float*)d_in[5];
    const float* Wfc = (const float*)d_in[6];
    const float* bfc = (const float*)d_in[7];
    float* out = (float*)d_out;

    cudaFuncSetAttribute(gemm_embed_mma,
                         cudaFuncAttributeMaxDynamicSharedMemorySize, SMEM_EMBED);
    cudaFuncSetAttribute(recurrent_persistent,
                         cudaFuncAttributeMaxDynamicSharedMemorySize, SMEM_PERSIST);
    cudaFuncSetAttribute(fc_kernel,
                         cudaFuncAttributeMaxDynamicSharedMemorySize, 16 * HIDDEN * 4);

    init_kernel<<<512, 256>>>();
    conv_emb<<<16000, 256>>>(emb);
    prep_weights<<<dim3(32, 64), dim3(32, 8)>>>(Wz, Wh);
    prep_win<<<dim3(16, 64), dim3(32, 8)>>>(Wz, Wh);
    gemm_embed_mma<<<dim3(16, 512), 256, SMEM_EMBED>>>(x, bz, bh);
    recurrent_persistent<<<NCTA, 256, SMEM_PERSIST>>>();
    fc_kernel<<<dim3(8, 8), 128, 16 * HIDDEN * 4>>>(Wfc, bfc, out);
}